// round 5
// baseline (speedup 1.0000x reference)
#include <cuda_runtime.h>
#include <cstdint>

// Problem constants
#define Bc 4
#define Nc 8192
#define Fc 64
#define Sc 2048
#define Kc 16
#define Cc 128
#define MTOT (Bc*Sc*Kc)          // 131072 rows through the MLP
#define GBLKS (MTOT/128)         // 1024 gemm blocks
#define FULLM 0xffffffffu

typedef unsigned long long ull;

// -------- scratch (static device allocations; no cudaMalloc allowed) --------
__device__ float g_h0[(size_t)MTOT*Cc];   // 64 MB, pre-BN layer0 output
__device__ float g_h1[(size_t)MTOT*Cc];   // 64 MB, pre-BN layer1 output
__device__ int   g_knn[Bc*Sc*Kc];
__device__ float g_partS0[Cc*GBLKS];      // [c][blk] coalesced for stats
__device__ float g_partQ0[Cc*GBLKS];
__device__ float g_partS1[Cc*GBLKS];
__device__ float g_partQ1[Cc*GBLKS];
__device__ float g_aff0[2*Cc];            // [a..., b...] affine for relu(bn)
__device__ float g_aff1[2*Cc];

// ---------------- f32x2 packed helpers (sm_100+) ----------------
__device__ __forceinline__ ull f2add(ull a, ull b){
    ull r; asm("add.rn.f32x2 %0,%1,%2;" : "=l"(r) : "l"(a), "l"(b)); return r;
}
__device__ __forceinline__ ull f2mul(ull a, ull b){
    ull r; asm("mul.rn.f32x2 %0,%1,%2;" : "=l"(r) : "l"(a), "l"(b)); return r;
}
__device__ __forceinline__ ull f2fma(ull a, ull b, ull c){
    ull r; asm("fma.rn.f32x2 %0,%1,%2,%3;" : "=l"(r) : "l"(a), "l"(b), "l"(c)); return r;
}
__device__ __forceinline__ ull fpack(float lo, float hi){
    ull r; asm("mov.b64 %0,{%1,%2};" : "=l"(r) : "f"(lo), "f"(hi)); return r;
}
__device__ __forceinline__ float2 funpack(ull p){
    float2 f; asm("mov.b64 {%0,%1},%2;" : "=f"(f.x), "=f"(f.y) : "l"(p)); return f;
}
__device__ __forceinline__ ull fdup_bits(float v){
    unsigned ub = __float_as_uint(v);
    return ((ull)ub << 32) | ub;
}

// ---------------- cluster helpers ----------------
__device__ __forceinline__ uint32_t smem_u32(const void* p){
    uint32_t a;
    asm("{ .reg .u64 t; cvta.to.shared.u64 t, %1; cvt.u32.u64 %0, t; }"
        : "=r"(a) : "l"(p));
    return a;
}
__device__ __forceinline__ uint32_t ctarank(){
    uint32_t r; asm("mov.u32 %0, %%cluster_ctarank;" : "=r"(r)); return r;
}
__device__ __forceinline__ void cluster_sync(){
    asm volatile("barrier.cluster.arrive.aligned;" ::: "memory");
    asm volatile("barrier.cluster.wait.aligned;" ::: "memory");
}
__device__ __forceinline__ uint32_t mapa_addr(uint32_t local, uint32_t peer){
    uint32_t r;
    asm("mapa.shared::cluster.u32 %0, %1, %2;" : "=r"(r) : "r"(local), "r"(peer));
    return r;
}
__device__ __forceinline__ void st_rel_cluster_u64(uint32_t raddr, ull v){
    asm volatile("st.release.cluster.shared::cluster.u64 [%0], %1;"
                 :: "r"(raddr), "l"(v) : "memory");
}
__device__ __forceinline__ ull ld_acq_cluster_u64(uint32_t addr){
    ull v;
    asm volatile("ld.acquire.cluster.shared::cta.u64 %0, [%1];"
                 : "=l"(v) : "r"(addr) : "memory");
    return v;
}
__device__ __forceinline__ unsigned redux_max_u32(unsigned v){
    unsigned r, m = FULLM;
    asm volatile("redux.sync.max.u32 %0, %1, %2;" : "=r"(r) : "r"(v), "r"(m));
    return r;
}

// ============================================================================
// 1) Farthest point sampling, 4-CTA cluster per batch, 256 thr x 8 pts.
//    Per iter: warp redux argmax -> 1 bar -> threads 0-3 serially max the 8
//    warp partials and publish a seq-tagged key via st.release.cluster to all
//    4 CTAs' slots -> every thread spin-polls its 4 LOCAL slots with
//    ld.acquire (no mbarrier, no post-exchange barrier).
//    Key = value_bits<<32 | (8191-idx)<<19 | seq(13b): compares value desc,
//    then smallest index (exact jnp.argmax tie-break); seq equal per iter.
//    All distance math bit-identical to reference.
// ============================================================================
#define FPS_CLUS 4
#define FPS_OFF_PART  (3*Nc*4)                 // ull[8]
#define FPS_OFF_SLOT  (FPS_OFF_PART + 8*8)     // ull[2][4]
#define FPS_SMEM      (FPS_OFF_SLOT + 2*4*8 + 16)

__global__ __launch_bounds__(256,1) __cluster_dims__(FPS_CLUS,1,1)
void fps_kernel(const float* __restrict__ xyz, float* __restrict__ out)
{
    extern __shared__ float smem_f[];
    float* X = smem_f;
    float* Y = smem_f + Nc;
    float* Z = smem_f + 2*Nc;
    const uint32_t sbase = smem_u32(smem_f);
    ull* part = (ull*)((char*)smem_f + FPS_OFF_PART);
    ull* slot = (ull*)((char*)smem_f + FPS_OFF_SLOT);   // [2][4]
    const uint32_t slot_a = sbase + FPS_OFF_SLOT;

    const int t = threadIdx.x;
    const int lane = t & 31, wid = t >> 5;
    const uint32_t rank = ctarank();
    const int b = blockIdx.x / FPS_CLUS;

    const float* base = xyz + (size_t)b*Nc*3;
    float* oxyz = out + (size_t)b*Sc*3;

    // full cloud copy for winner lookup
    for (int p = t; p < Nc; p += 256) {
        X[p] = base[p*3+0]; Y[p] = base[p*3+1]; Z[p] = base[p*3+2];
    }
    if (t < 8) slot[t] = 0;    // seq starts at 1, 0 never matches
    __syncthreads();
    cluster_sync();            // smem + zeroed slots visible cluster-wide

    // this CTA's 8 points/thread, packed pairs
    const int pbase = (int)rank*2048 + t*8;
    ull px2[4], py2[4], pz2[4];
    float md[8];
#pragma unroll
    for (int jj = 0; jj < 4; jj++) {
        int p = pbase + jj*2;
        px2[jj] = fpack(X[p], X[p+1]);
        py2[jj] = fpack(Y[p], Y[p+1]);
        pz2[jj] = fpack(Z[p], Z[p+1]);
        md[2*jj] = 1e10f; md[2*jj+1] = 1e10f;
    }

    float cx = X[0], cy = Y[0], cz = Z[0];

    for (int s = 0; s < Sc; s++) {
        if (rank == 0 && t == 0) {
            oxyz[s*3+0]=cx; oxyz[s*3+1]=cy; oxyz[s*3+2]=cz;
        }
        if (s == Sc-1) break;

        // x - c == x + (-c) exactly in IEEE754
        ull ncx = fdup_bits(-cx), ncy = fdup_bits(-cy), ncz = fdup_bits(-cz);

        float best = -1.0f; int bidx = 0;
#pragma unroll
        for (int jj = 0; jj < 4; jj++) {
            ull dx = f2add(px2[jj], ncx);
            ull dy = f2add(py2[jj], ncy);
            ull dz = f2add(pz2[jj], ncz);
            ull d2 = f2add(f2add(f2mul(dx,dx), f2mul(dy,dy)), f2mul(dz,dz));
            float2 d = funpack(d2);
            float m0 = fminf(md[2*jj],   d.x); md[2*jj]   = m0;
            float m1 = fminf(md[2*jj+1], d.y); md[2*jj+1] = m1;
            if (m0 > best) { best = m0; bidx = pbase + 2*jj; }
            if (m1 > best) { best = m1; bidx = pbase + 2*jj + 1; }
        }

        // warp argmax: values >= +0 so float bits are order-monotone
        unsigned ub = __float_as_uint(best);
        unsigned wb = redux_max_u32(ub);
        unsigned bal = __ballot_sync(FULLM, ub == wb);
        int src = __ffs(bal) - 1;                 // lane order == index order
        int widx = __shfl_sync(FULLM, bidx, src);
        if (lane == 0)
            part[wid] = ((ull)wb << 32) | ((ull)(unsigned)(8191 - widx) << 19);
        __syncthreads();

        const int ib = s & 1;
        const ull seq = (ull)(unsigned)((s + 1) & 0x1FFF);

        if (t < FPS_CLUS) {                       // threads 0-3 publish
            ull k = part[0];
#pragma unroll
            for (int i = 1; i < 8; i++) { ull o = part[i]; if (o > k) k = o; }
            k |= seq;
            uint32_t ra = mapa_addr(slot_a + (ib*4 + rank)*8, (uint32_t)t);
            st_rel_cluster_u64(ra, k);
        }

        // spin on local slots until all 4 carry this iteration's seq
        const uint32_t la = slot_a + ib*32;
        ull k0, k1, k2, k3;
        do { k0 = ld_acq_cluster_u64(la);      } while ((k0 & 0x1FFFull) != seq);
        do { k1 = ld_acq_cluster_u64(la + 8);  } while ((k1 & 0x1FFFull) != seq);
        do { k2 = ld_acq_cluster_u64(la + 16); } while ((k2 & 0x1FFFull) != seq);
        do { k3 = ld_acq_cluster_u64(la + 24); } while ((k3 & 0x1FFFull) != seq);

        ull ka = (k0 > k1) ? k0 : k1;
        ull kb = (k2 > k3) ? k2 : k3;
        ull kw = (ka > kb) ? ka : kb;
        int w = 8191 - (int)((kw >> 19) & 0x1FFF);
        cx = X[w]; cy = Y[w]; cz = Z[w];
    }
    cluster_sync();
}

// ============================================================================
// 2) Brute-force KNN (K=16). 64 queries per CTA, 4 threads per query, each
//    scans a 2048-point chunk; exact lex-ordered merge of 4 stable top-16s.
//    d2 = (|q|^2 + |p|^2) - 2*q.p   (exact ref op order; d2 is never -0)
// ============================================================================
#define KNN_SMEM (Nc*16 + 64*64*8)

__device__ __forceinline__ unsigned okey(float f){
    unsigned u = __float_as_uint(f);
    return ((int)u < 0) ? ~u : (u | 0x80000000u);   // monotone order-preserving
}

__global__ __launch_bounds__(256,1) void knn_kernel(const float* __restrict__ xyz,
                                                    const float* __restrict__ newxyz)
{
    extern __shared__ float smem_f[];
    float4* tile = (float4*)smem_f;
    ull* merge = (ull*)(smem_f + Nc*4);
    const int blk = blockIdx.x;      // 128 blocks = 4 batches * 32
    const int b = blk >> 5;
    const int qbase = (blk & 31) * 64;
    const float* base = xyz + (size_t)b*Nc*3;

    for (int p = threadIdx.x; p < Nc; p += 256) {
        float x = base[p*3], y = base[p*3+1], z = base[p*3+2];
        float sq = __fadd_rn(__fadd_rn(__fmul_rn(x,x), __fmul_rn(y,y)), __fmul_rn(z,z));
        tile[p] = make_float4(x, y, z, sq);
    }
    __syncthreads();

    const int q = threadIdx.x & 63;
    const int ch = threadIdx.x >> 6;             // chunk 0..3
    const int qi = b*Sc + qbase + q;
    float qx = newxyz[qi*3], qy = newxyz[qi*3+1], qz = newxyz[qi*3+2];
    float sqq = __fadd_rn(__fadd_rn(__fmul_rn(qx,qx), __fmul_rn(qy,qy)), __fmul_rn(qz,qz));

    float dist[Kc]; int ids[Kc];
#pragma unroll
    for (int i = 0; i < Kc; i++) { dist[i] = 3.4e38f; ids[i] = 0; }
    float kth = 3.4e38f;

    const int p0 = ch*2048;
    for (int p = p0; p < p0 + 2048; p++) {
        float4 v = tile[p];
        float dot = __fadd_rn(__fadd_rn(__fmul_rn(qx,v.x), __fmul_rn(qy,v.y)),
                              __fmul_rn(qz,v.z));
        float d2 = __fsub_rn(__fadd_rn(sqq, v.w), __fadd_rn(dot, dot));
        if (d2 < kth) {
            int j = Kc-1;
            while (j > 0 && dist[j-1] > d2) {   // stable insertion
                dist[j] = dist[j-1]; ids[j] = ids[j-1]; j--;
            }
            dist[j] = d2; ids[j] = p;
            kth = dist[Kc-1];
        }
    }
    // store lex-sorted packed list
    ull* mylist = merge + q*64 + ch*16;
#pragma unroll
    for (int i = 0; i < Kc; i++)
        mylist[i] = ((ull)okey(dist[i]) << 32) | (unsigned)ids[i];
    __syncthreads();

    if (threadIdx.x < 64) {
        int mq = threadIdx.x;
        const ull* L = merge + mq*64;
        int h0 = 0, h1 = 16, h2 = 32, h3 = 48;
        int oq = (b*Sc + qbase + mq)*Kc;
#pragma unroll
        for (int r = 0; r < Kc; r++) {
            ull k0 = L[h0], k1 = L[h1], k2 = L[h2], k3 = L[h3];
            ull ka = (k0 <= k1) ? k0 : k1;
            ull kb = (k2 <= k3) ? k2 : k3;
            ull kw = (ka <= kb) ? ka : kb;
            g_knn[oq + r] = (int)(unsigned)kw;
            if (kw == k0) h0++; else if (kw == k1) h1++;
            else if (kw == k2) h2++; else h3++;
        }
    }
}

// ============================================================================
// 3) Gather + layer0 GEMM (M=131072, N=128, K=67) + BN-stat partials.
//    128x128 tile, 256 threads, 8x8 microtiles, packed f32x2 FFMA.
//    A stored duplicated (v,v) in smem so no per-k register dup.
// ============================================================================
#define G0_SMEM (68*128*8 + 68*128*4)

__global__ __launch_bounds__(256,2) void gemm0_kernel(const float* __restrict__ xyz,
                                                      const float* __restrict__ feat,
                                                      const float* __restrict__ w0,
                                                      const float* __restrict__ b0,
                                                      const float* __restrict__ newxyz)
{
    extern __shared__ float smem_f[];
    ull*   AD = (ull*)smem_f;                      // [68][128] dup-packed
    float* WS = smem_f + 68*128*2;                 // [68][128]
    const int t = threadIdx.x;
    const int blk = blockIdx.x;

    for (int i = t; i < Cc*67; i += 256) {         // w0: [C][67]
        int c = i / 67, f = i - c*67;
        WS[f*128 + c] = w0[i];
    }
    {
        int m = t & 127, half = t >> 7;
        int R = blk*128 + m;
        int bs = R >> 4;
        int b = bs >> 11;
        int nid = g_knn[R];
        const float* frow = feat + ((size_t)b*Nc + nid)*Fc;
        if (half == 0) {
            const float* prow = xyz + ((size_t)b*Nc + nid)*3;
            AD[0*128+m] = fdup_bits(__fsub_rn(prow[0], newxyz[bs*3+0]));
            AD[1*128+m] = fdup_bits(__fsub_rn(prow[1], newxyz[bs*3+1]));
            AD[2*128+m] = fdup_bits(__fsub_rn(prow[2], newxyz[bs*3+2]));
            for (int f = 0; f < 32; f += 4) {
                float4 v = *(const float4*)(frow + f);
                AD[(3+f)*128+m]=fdup_bits(v.x); AD[(4+f)*128+m]=fdup_bits(v.y);
                AD[(5+f)*128+m]=fdup_bits(v.z); AD[(6+f)*128+m]=fdup_bits(v.w);
            }
        } else {
            for (int f = 32; f < 64; f += 4) {
                float4 v = *(const float4*)(frow + f);
                AD[(3+f)*128+m]=fdup_bits(v.x); AD[(4+f)*128+m]=fdup_bits(v.y);
                AD[(5+f)*128+m]=fdup_bits(v.z); AD[(6+f)*128+m]=fdup_bits(v.w);
            }
        }
    }
    __syncthreads();

    const int tn = t & 15, tm = t >> 4;
    ull accp[8][4];
#pragma unroll
    for (int i = 0; i < 8; i++)
#pragma unroll
        for (int j = 0; j < 4; j++) accp[i][j] = 0;

    for (int kk = 0; kk < 67; kk++) {
        ulonglong2 a01 = *(const ulonglong2*)(AD + kk*128 + tm*8);
        ulonglong2 a23 = *(const ulonglong2*)(AD + kk*128 + tm*8 + 2);
        ulonglong2 a45 = *(const ulonglong2*)(AD + kk*128 + tm*8 + 4);
        ulonglong2 a67 = *(const ulonglong2*)(AD + kk*128 + tm*8 + 6);
        ulonglong2 wA  = *(const ulonglong2*)(WS + kk*128 + tn*8);
        ulonglong2 wB  = *(const ulonglong2*)(WS + kk*128 + tn*8 + 4);
        ull a[8] = {a01.x,a01.y,a23.x,a23.y,a45.x,a45.y,a67.x,a67.y};
        ull w[4] = {wA.x, wA.y, wB.x, wB.y};
#pragma unroll
        for (int i = 0; i < 8; i++)
#pragma unroll
            for (int j = 0; j < 4; j++) accp[i][j] = f2fma(a[i], w[j], accp[i][j]);
    }

    float bb[8], sum[8], ssq[8];
#pragma unroll
    for (int j = 0; j < 8; j++) { bb[j] = b0[tn*8+j]; sum[j]=0.f; ssq[j]=0.f; }
#pragma unroll
    for (int i = 0; i < 8; i++) {
        size_t row = (size_t)blk*128 + tm*8 + i;
        float v[8];
#pragma unroll
        for (int j = 0; j < 4; j++) {
            float2 u = funpack(accp[i][j]);
            v[2*j]   = __fadd_rn(u.x, bb[2*j]);
            v[2*j+1] = __fadd_rn(u.y, bb[2*j+1]);
        }
#pragma unroll
        for (int j = 0; j < 8; j++) {
            sum[j] += v[j];
            ssq[j] = fmaf(v[j], v[j], ssq[j]);
        }
        *(float4*)&g_h0[row*Cc + tn*8]     = make_float4(v[0],v[1],v[2],v[3]);
        *(float4*)&g_h0[row*Cc + tn*8 + 4] = make_float4(v[4],v[5],v[6],v[7]);
    }
    __syncthreads();
    float* st = smem_f;                     // reuse: [128ch][16tm] sum, +2048 ssq
#pragma unroll
    for (int j = 0; j < 8; j++) {
        st[(tn*8+j)*16 + tm]        = sum[j];
        st[2048 + (tn*8+j)*16 + tm] = ssq[j];
    }
    __syncthreads();
    if (t < Cc) {
        float s = 0.f, q = 0.f;
        for (int r = 0; r < 16; r++) { s += st[t*16+r]; q += st[2048 + t*16 + r]; }
        g_partS0[t*GBLKS + blk] = s;
        g_partQ0[t*GBLKS + blk] = q;
    }
}

// ============================================================================
// 4) BN stat reduce -> affine. 128 blocks (one per channel) x 256 threads,
//    coalesced reads, deterministic fp64 accumulation.
// ============================================================================
__global__ __launch_bounds__(256) void stats_kernel(int layer,
                                                    const float* __restrict__ gamma,
                                                    const float* __restrict__ beta)
{
    const float* PS = layer ? g_partS1 : g_partS0;
    const float* PQ = layer ? g_partQ1 : g_partQ0;
    float* aff = layer ? g_aff1 : g_aff0;
    const int c = blockIdx.x;
    const int t = threadIdx.x;
    double s = 0.0, q = 0.0;
    for (int i = t; i < GBLKS; i += 256) {
        s += (double)PS[c*GBLKS + i];
        q += (double)PQ[c*GBLKS + i];
    }
#pragma unroll
    for (int o = 16; o; o >>= 1) {
        s += __shfl_xor_sync(FULLM, s, o);
        q += __shfl_xor_sync(FULLM, q, o);
    }
    __shared__ double sw[16];
    int lane = t & 31, wid = t >> 5;
    if (lane == 0) { sw[wid*2] = s; sw[wid*2+1] = q; }
    __syncthreads();
    if (t == 0) {
        double S = 0.0, Q = 0.0;
        for (int w = 0; w < 8; w++) { S += sw[w*2]; Q += sw[w*2+1]; }
        double cnt = (double)MTOT;
        double mean = S / cnt;
        double var = Q / cnt - mean*mean;
        float a = gamma[c] * (float)(1.0 / sqrt(var + 1e-5));
        aff[c] = a;
        aff[Cc + c] = __fsub_rn(beta[c], (float)mean * a);
    }
}

// ============================================================================
// 5) Layer1 GEMM (K=128): A = relu(affine0(h0)) dup-packed, W = w1. + BN1.
// ============================================================================
#define G1_SMEM (128*128*8 + 128*128*4)

__global__ __launch_bounds__(256,1) void gemm1_kernel(const float* __restrict__ w1,
                                                      const float* __restrict__ b1)
{
    extern __shared__ float smem_f[];
    ull*   AD = (ull*)smem_f;                      // [128][128] dup-packed
    float* WS = smem_f + 128*128*2;                // [128][128]
    const int t = threadIdx.x;
    const int blk = blockIdx.x;

    for (int i = t; i < Cc*Cc; i += 256) {         // w1: [C][C]
        int c = i >> 7, f = i & 127;
        WS[f*128 + c] = w1[i];
    }
    {
        int m = t & 127, half = t >> 7;
        size_t R = (size_t)blk*128 + m;
        const float* hrow = g_h0 + R*Cc + half*64;
        for (int f = 0; f < 64; f += 4) {
            float4 v = *(const float4*)(hrow + f);
            int fg = half*64 + f;
            AD[(fg+0)*128+m] = fdup_bits(fmaxf(fmaf(g_aff0[fg+0], v.x, g_aff0[Cc+fg+0]), 0.f));
            AD[(fg+1)*128+m] = fdup_bits(fmaxf(fmaf(g_aff0[fg+1], v.y, g_aff0[Cc+fg+1]), 0.f));
            AD[(fg+2)*128+m] = fdup_bits(fmaxf(fmaf(g_aff0[fg+2], v.z, g_aff0[Cc+fg+2]), 0.f));
            AD[(fg+3)*128+m] = fdup_bits(fmaxf(fmaf(g_aff0[fg+3], v.w, g_aff0[Cc+fg+3]), 0.f));
        }
    }
    __syncthreads();

    const int tn = t & 15, tm = t >> 4;
    ull accp[8][4];
#pragma unroll
    for (int i = 0; i < 8; i++)
#pragma unroll
        for (int j = 0; j < 4; j++) accp[i][j] = 0;

    for (int kk = 0; kk < Cc; kk++) {
        ulonglong2 a01 = *(const ulonglong2*)(AD + kk*128 + tm*8);
        ulonglong2 a23 = *(const ulonglong2*)(AD + kk*128 + tm*8 + 2);
        ulonglong2 a45 = *(const ulonglong2*)(AD + kk*128 + tm*8 + 4);
        ulonglong2 a67 = *(const ulonglong2*)(AD + kk*128 + tm*8 + 6);
        ulonglong2 wA  = *(const ulonglong2*)(WS + kk*128 + tn*8);
        ulonglong2 wB  = *(const ulonglong2*)(WS + kk*128 + tn*8 + 4);
        ull a[8] = {a01.x,a01.y,a23.x,a23.y,a45.x,a45.y,a67.x,a67.y};
        ull w[4] = {wA.x, wA.y, wB.x, wB.y};
#pragma unroll
        for (int i = 0; i < 8; i++)
#pragma unroll
            for (int j = 0; j < 4; j++) accp[i][j] = f2fma(a[i], w[j], accp[i][j]);
    }

    float bb[8], sum[8], ssq[8];
#pragma unroll
    for (int j = 0; j < 8; j++) { bb[j] = b1[tn*8+j]; sum[j]=0.f; ssq[j]=0.f; }
#pragma unroll
    for (int i = 0; i < 8; i++) {
        size_t row = (size_t)blk*128 + tm*8 + i;
        float v[8];
#pragma unroll
        for (int j = 0; j < 4; j++) {
            float2 u = funpack(accp[i][j]);
            v[2*j]   = __fadd_rn(u.x, bb[2*j]);
            v[2*j+1] = __fadd_rn(u.y, bb[2*j+1]);
        }
#pragma unroll
        for (int j = 0; j < 8; j++) {
            sum[j] += v[j];
            ssq[j] = fmaf(v[j], v[j], ssq[j]);
        }
        *(float4*)&g_h1[row*Cc + tn*8]     = make_float4(v[0],v[1],v[2],v[3]);
        *(float4*)&g_h1[row*Cc + tn*8 + 4] = make_float4(v[4],v[5],v[6],v[7]);
    }
    __syncthreads();
    float* st = smem_f;
#pragma unroll
    for (int j = 0; j < 8; j++) {
        st[(tn*8+j)*16 + tm]        = sum[j];
        st[2048 + (tn*8+j)*16 + tm] = ssq[j];
    }
    __syncthreads();
    if (t < Cc) {
        float s = 0.f, q = 0.f;
        for (int r = 0; r < 16; r++) { s += st[t*16+r]; q += st[2048 + t*16 + r]; }
        g_partS1[t*GBLKS + blk] = s;
        g_partQ1[t*GBLKS + blk] = q;
    }
}

// ============================================================================
// 6) relu(affine1(h1)) then max over K -> new_features
// ============================================================================
__global__ __launch_bounds__(256) void final_kernel(float* __restrict__ out)
{
    int gid = blockIdx.x*256 + threadIdx.x;     // B*S*C = 1,048,576
    int c = gid & 127, bs = gid >> 7;
    float a = g_aff1[c], b = g_aff1[Cc + c];
    float m = -3.4e38f;
#pragma unroll
    for (int k = 0; k < Kc; k++) {
        float h = g_h1[((size_t)(bs*Kc + k))*Cc + c];
        float v = fmaxf(fmaf(a, h, b), 0.f);
        m = fmaxf(m, v);
    }
    out[Bc*Sc*3 + gid] = m;
}

// ============================================================================
extern "C" void kernel_launch(void* const* d_in, const int* in_sizes, int n_in,
                              void* d_out, int out_size)
{
    const float* xyz  = (const float*)d_in[0];
    const float* feat = (const float*)d_in[1];
    const float* w0   = (const float*)d_in[2];
    const float* b0   = (const float*)d_in[3];
    const float* g0   = (const float*)d_in[4];
    const float* be0  = (const float*)d_in[5];
    const float* w1   = (const float*)d_in[6];
    const float* b1   = (const float*)d_in[7];
    const float* g1   = (const float*)d_in[8];
    const float* be1  = (const float*)d_in[9];
    float* out = (float*)d_out;

    cudaFuncSetAttribute(fps_kernel,   cudaFuncAttributeMaxDynamicSharedMemorySize, FPS_SMEM);
    cudaFuncSetAttribute(knn_kernel,   cudaFuncAttributeMaxDynamicSharedMemorySize, KNN_SMEM);
    cudaFuncSetAttribute(gemm0_kernel, cudaFuncAttributeMaxDynamicSharedMemorySize, G0_SMEM);
    cudaFuncSetAttribute(gemm1_kernel, cudaFuncAttributeMaxDynamicSharedMemorySize, G1_SMEM);

    fps_kernel  <<<Bc*FPS_CLUS, 256, FPS_SMEM>>>(xyz, out);
    knn_kernel  <<<128, 256, KNN_SMEM>>>(xyz, out);
    gemm0_kernel<<<GBLKS, 256, G0_SMEM>>>(xyz, feat, w0, b0, out);
    stats_kernel<<<Cc, 256>>>(0, g0, be0);
    gemm1_kernel<<<GBLKS, 256, G1_SMEM>>>(w1, b1);
    stats_kernel<<<Cc, 256>>>(1, g1, be1);
    final_kernel<<<(Bc*Sc*Cc)/256, 256>>>(out);
}

// round 6
// speedup vs baseline: 1.1749x; 1.1749x over previous
#include <cuda_runtime.h>
#include <cstdint>

// Problem constants
#define Bc 4
#define Nc 8192
#define Fc 64
#define Sc 2048
#define Kc 16
#define Cc 128
#define MTOT (Bc*Sc*Kc)          // 131072 rows through the MLP
#define GBLKS (MTOT/128)         // 1024 gemm blocks
#define FULLM 0xffffffffu

typedef unsigned long long ull;

// -------- scratch (static device allocations; no cudaMalloc allowed) --------
__device__ float g_h0[(size_t)MTOT*Cc];   // 64 MB, pre-BN layer0 output
__device__ float g_h1[(size_t)MTOT*Cc];   // 64 MB, pre-BN layer1 output
__device__ int   g_knn[Bc*Sc*Kc];
__device__ float g_partS0[Cc*GBLKS];      // [c][blk] coalesced for stats
__device__ float g_partQ0[Cc*GBLKS];
__device__ float g_partS1[Cc*GBLKS];
__device__ float g_partQ1[Cc*GBLKS];
__device__ float g_aff0[2*Cc];            // [a..., b...] affine for relu(bn)
__device__ float g_aff1[2*Cc];

// ---------------- f32x2 packed helpers (sm_100+) ----------------
__device__ __forceinline__ ull f2add(ull a, ull b){
    ull r; asm("add.rn.f32x2 %0,%1,%2;" : "=l"(r) : "l"(a), "l"(b)); return r;
}
__device__ __forceinline__ ull f2mul(ull a, ull b){
    ull r; asm("mul.rn.f32x2 %0,%1,%2;" : "=l"(r) : "l"(a), "l"(b)); return r;
}
__device__ __forceinline__ ull f2fma(ull a, ull b, ull c){
    ull r; asm("fma.rn.f32x2 %0,%1,%2,%3;" : "=l"(r) : "l"(a), "l"(b), "l"(c)); return r;
}
__device__ __forceinline__ ull fpack(float lo, float hi){
    ull r; asm("mov.b64 %0,{%1,%2};" : "=l"(r) : "f"(lo), "f"(hi)); return r;
}
__device__ __forceinline__ float2 funpack(ull p){
    float2 f; asm("mov.b64 {%0,%1},%2;" : "=f"(f.x), "=f"(f.y) : "l"(p)); return f;
}
__device__ __forceinline__ ull fdup_bits(float v){
    unsigned ub = __float_as_uint(v);
    return ((ull)ub << 32) | ub;
}

// ---------------- warp redux helpers (Ampere+) ----------------
__device__ __forceinline__ unsigned redux_max_u32(unsigned v){
    unsigned r, m = FULLM;
    asm volatile("redux.sync.max.u32 %0, %1, %2;" : "=r"(r) : "r"(v), "r"(m));
    return r;
}
__device__ __forceinline__ unsigned redux_min_u32(unsigned v){
    unsigned r, m = FULLM;
    asm volatile("redux.sync.min.u32 %0, %1, %2;" : "=r"(r) : "r"(v), "r"(m));
    return r;
}

// ============================================================================
// 1) Farthest point sampling. One CTA per batch, 1024 thr x 8 pts/thread.
//    Per iter: (a) packed f32x2 distance+min update, scalar argmax track;
//    (b) stage1 warp argmax via redux.max(valbits)+redux.min(idx among ties);
//    (c) one __syncthreads; (d) stage2: every warp loads the 32 warp partials
//    and repeats the redux pair (no second barrier, no shfl butterflies).
//    Bit-exact: d=((dx*dx+dy*dy)+dz*dz), min_d=min(md,d), first-index ties
//    (values >= +0 so float bits are order-monotone; lane order==idx order).
// ============================================================================
#define FPS_OFF_PART  (3*Nc*4)                 // ull[2][32]
#define FPS_SMEM      (FPS_OFF_PART + 2*32*8)

__global__ __launch_bounds__(1024,1) void fps_kernel(const float* __restrict__ xyz,
                                                     float* __restrict__ out)
{
    extern __shared__ float smem_f[];
    float* X = smem_f;
    float* Y = smem_f + Nc;
    float* Z = smem_f + 2*Nc;
    ull* part = (ull*)((char*)smem_f + FPS_OFF_PART);   // [2][32]

    const int b = blockIdx.x;
    const float* base = xyz + (size_t)b*Nc*3;
    float* oxyz = out + (size_t)b*Sc*3;
    const int t = threadIdx.x;
    const int lane = t & 31, wid = t >> 5;

    for (int p = t; p < Nc; p += 1024) {
        X[p] = base[p*3+0]; Y[p] = base[p*3+1]; Z[p] = base[p*3+2];
    }
    __syncthreads();

    // 8 points/thread as 4 packed pairs
    const int pbase = t*8;
    ull px2[4], py2[4], pz2[4];
    float md[8];
#pragma unroll
    for (int jj = 0; jj < 4; jj++) {
        int p = pbase + jj*2;
        px2[jj] = fpack(X[p], X[p+1]);
        py2[jj] = fpack(Y[p], Y[p+1]);
        pz2[jj] = fpack(Z[p], Z[p+1]);
        md[2*jj] = 1e10f; md[2*jj+1] = 1e10f;
    }

    float cx = X[0], cy = Y[0], cz = Z[0];

    for (int s = 0; s < Sc; s++) {
        if (t == 0) {
            oxyz[s*3+0]=cx; oxyz[s*3+1]=cy; oxyz[s*3+2]=cz;
        }
        if (s == Sc-1) break;

        // x - c == x + (-c) exactly in IEEE754
        ull ncx = fdup_bits(-cx), ncy = fdup_bits(-cy), ncz = fdup_bits(-cz);

        float best = -1.0f; int bidx = 0;
#pragma unroll
        for (int jj = 0; jj < 4; jj++) {
            ull dx = f2add(px2[jj], ncx);
            ull dy = f2add(py2[jj], ncy);
            ull dz = f2add(pz2[jj], ncz);
            ull d2 = f2add(f2add(f2mul(dx,dx), f2mul(dy,dy)), f2mul(dz,dz));
            float2 d = funpack(d2);
            float m0 = fminf(md[2*jj],   d.x); md[2*jj]   = m0;
            float m1 = fminf(md[2*jj+1], d.y); md[2*jj+1] = m1;
            if (m0 > best) { best = m0; bidx = pbase + 2*jj; }      // strict >
            if (m1 > best) { best = m1; bidx = pbase + 2*jj + 1; }
        }

        // stage 1: warp argmax (value desc, then smallest index)
        unsigned ub = __float_as_uint(best);
        unsigned wb = redux_max_u32(ub);
        unsigned cand = (ub == wb) ? (unsigned)bidx : FULLM;
        unsigned wi = redux_min_u32(cand);

        const int ib = s & 1;                    // double-buffered partials
        if (lane == 0) part[ib*32 + wid] = ((ull)wb << 32) | wi;
        __syncthreads();

        // stage 2: every warp reduces the 32 warp partials (warp slot order
        // == ascending index blocks, so min-index tie-break stays exact)
        ull k = part[ib*32 + lane];
        unsigned v = (unsigned)(k >> 32);
        unsigned vm = redux_max_u32(v);
        unsigned c2 = (v == vm) ? (unsigned)k : FULLM;
        unsigned w = redux_min_u32(c2);

        cx = X[w]; cy = Y[w]; cz = Z[w];
    }
}

// ============================================================================
// 2) Brute-force KNN (K=16). 64 queries per CTA, 4 threads per query, each
//    scans a 2048-point chunk; exact lex-ordered merge of 4 stable top-16s.
//    d2 = (|q|^2 + |p|^2) - 2*q.p   (exact ref op order; d2 is never -0)
// ============================================================================
#define KNN_SMEM (Nc*16 + 64*64*8)

__device__ __forceinline__ unsigned okey(float f){
    unsigned u = __float_as_uint(f);
    return ((int)u < 0) ? ~u : (u | 0x80000000u);   // monotone order-preserving
}

__global__ __launch_bounds__(256,1) void knn_kernel(const float* __restrict__ xyz,
                                                    const float* __restrict__ newxyz)
{
    extern __shared__ float smem_f[];
    float4* tile = (float4*)smem_f;
    ull* merge = (ull*)(smem_f + Nc*4);
    const int blk = blockIdx.x;      // 128 blocks = 4 batches * 32
    const int b = blk >> 5;
    const int qbase = (blk & 31) * 64;
    const float* base = xyz + (size_t)b*Nc*3;

    for (int p = threadIdx.x; p < Nc; p += 256) {
        float x = base[p*3], y = base[p*3+1], z = base[p*3+2];
        float sq = __fadd_rn(__fadd_rn(__fmul_rn(x,x), __fmul_rn(y,y)), __fmul_rn(z,z));
        tile[p] = make_float4(x, y, z, sq);
    }
    __syncthreads();

    const int q = threadIdx.x & 63;
    const int ch = threadIdx.x >> 6;             // chunk 0..3
    const int qi = b*Sc + qbase + q;
    float qx = newxyz[qi*3], qy = newxyz[qi*3+1], qz = newxyz[qi*3+2];
    float sqq = __fadd_rn(__fadd_rn(__fmul_rn(qx,qx), __fmul_rn(qy,qy)), __fmul_rn(qz,qz));

    float dist[Kc]; int ids[Kc];
#pragma unroll
    for (int i = 0; i < Kc; i++) { dist[i] = 3.4e38f; ids[i] = 0; }
    float kth = 3.4e38f;

    const int p0 = ch*2048;
    for (int p = p0; p < p0 + 2048; p++) {
        float4 v = tile[p];
        float dot = __fadd_rn(__fadd_rn(__fmul_rn(qx,v.x), __fmul_rn(qy,v.y)),
                              __fmul_rn(qz,v.z));
        float d2 = __fsub_rn(__fadd_rn(sqq, v.w), __fadd_rn(dot, dot));
        if (d2 < kth) {
            int j = Kc-1;
            while (j > 0 && dist[j-1] > d2) {   // stable insertion
                dist[j] = dist[j-1]; ids[j] = ids[j-1]; j--;
            }
            dist[j] = d2; ids[j] = p;
            kth = dist[Kc-1];
        }
    }
    // store lex-sorted packed list
    ull* mylist = merge + q*64 + ch*16;
#pragma unroll
    for (int i = 0; i < Kc; i++)
        mylist[i] = ((ull)okey(dist[i]) << 32) | (unsigned)ids[i];
    __syncthreads();

    if (threadIdx.x < 64) {
        int mq = threadIdx.x;
        const ull* L = merge + mq*64;
        int h0 = 0, h1 = 16, h2 = 32, h3 = 48;
        int oq = (b*Sc + qbase + mq)*Kc;
#pragma unroll
        for (int r = 0; r < Kc; r++) {
            ull k0 = L[h0], k1 = L[h1], k2 = L[h2], k3 = L[h3];
            ull ka = (k0 <= k1) ? k0 : k1;
            ull kb = (k2 <= k3) ? k2 : k3;
            ull kw = (ka <= kb) ? ka : kb;
            g_knn[oq + r] = (int)(unsigned)kw;
            if (kw == k0) h0++; else if (kw == k1) h1++;
            else if (kw == k2) h2++; else h3++;
        }
    }
}

// ============================================================================
// 3) Gather + layer0 GEMM (M=131072, N=128, K=67) + BN-stat partials.
//    128x128 tile, 256 threads, 8x8 microtiles, packed f32x2 FFMA.
//    A stored duplicated (v,v) in smem so no per-k register dup.
// ============================================================================
#define G0_SMEM (68*128*8 + 68*128*4)

__global__ __launch_bounds__(256,2) void gemm0_kernel(const float* __restrict__ xyz,
                                                      const float* __restrict__ feat,
                                                      const float* __restrict__ w0,
                                                      const float* __restrict__ b0,
                                                      const float* __restrict__ newxyz)
{
    extern __shared__ float smem_f[];
    ull*   AD = (ull*)smem_f;                      // [68][128] dup-packed
    float* WS = smem_f + 68*128*2;                 // [68][128]
    const int t = threadIdx.x;
    const int blk = blockIdx.x;

    for (int i = t; i < Cc*67; i += 256) {         // w0: [C][67]
        int c = i / 67, f = i - c*67;
        WS[f*128 + c] = w0[i];
    }
    {
        int m = t & 127, half = t >> 7;
        int R = blk*128 + m;
        int bs = R >> 4;
        int b = bs >> 11;
        int nid = g_knn[R];
        const float* frow = feat + ((size_t)b*Nc + nid)*Fc;
        if (half == 0) {
            const float* prow = xyz + ((size_t)b*Nc + nid)*3;
            AD[0*128+m] = fdup_bits(__fsub_rn(prow[0], newxyz[bs*3+0]));
            AD[1*128+m] = fdup_bits(__fsub_rn(prow[1], newxyz[bs*3+1]));
            AD[2*128+m] = fdup_bits(__fsub_rn(prow[2], newxyz[bs*3+2]));
            for (int f = 0; f < 32; f += 4) {
                float4 v = *(const float4*)(frow + f);
                AD[(3+f)*128+m]=fdup_bits(v.x); AD[(4+f)*128+m]=fdup_bits(v.y);
                AD[(5+f)*128+m]=fdup_bits(v.z); AD[(6+f)*128+m]=fdup_bits(v.w);
            }
        } else {
            for (int f = 32; f < 64; f += 4) {
                float4 v = *(const float4*)(frow + f);
                AD[(3+f)*128+m]=fdup_bits(v.x); AD[(4+f)*128+m]=fdup_bits(v.y);
                AD[(5+f)*128+m]=fdup_bits(v.z); AD[(6+f)*128+m]=fdup_bits(v.w);
            }
        }
    }
    __syncthreads();

    const int tn = t & 15, tm = t >> 4;
    ull accp[8][4];
#pragma unroll
    for (int i = 0; i < 8; i++)
#pragma unroll
        for (int j = 0; j < 4; j++) accp[i][j] = 0;

    for (int kk = 0; kk < 67; kk++) {
        ulonglong2 a01 = *(const ulonglong2*)(AD + kk*128 + tm*8);
        ulonglong2 a23 = *(const ulonglong2*)(AD + kk*128 + tm*8 + 2);
        ulonglong2 a45 = *(const ulonglong2*)(AD + kk*128 + tm*8 + 4);
        ulonglong2 a67 = *(const ulonglong2*)(AD + kk*128 + tm*8 + 6);
        ulonglong2 wA  = *(const ulonglong2*)(WS + kk*128 + tn*8);
        ulonglong2 wB  = *(const ulonglong2*)(WS + kk*128 + tn*8 + 4);
        ull a[8] = {a01.x,a01.y,a23.x,a23.y,a45.x,a45.y,a67.x,a67.y};
        ull w[4] = {wA.x, wA.y, wB.x, wB.y};
#pragma unroll
        for (int i = 0; i < 8; i++)
#pragma unroll
            for (int j = 0; j < 4; j++) accp[i][j] = f2fma(a[i], w[j], accp[i][j]);
    }

    float bb[8], sum[8], ssq[8];
#pragma unroll
    for (int j = 0; j < 8; j++) { bb[j] = b0[tn*8+j]; sum[j]=0.f; ssq[j]=0.f; }
#pragma unroll
    for (int i = 0; i < 8; i++) {
        size_t row = (size_t)blk*128 + tm*8 + i;
        float v[8];
#pragma unroll
        for (int j = 0; j < 4; j++) {
            float2 u = funpack(accp[i][j]);
            v[2*j]   = __fadd_rn(u.x, bb[2*j]);
            v[2*j+1] = __fadd_rn(u.y, bb[2*j+1]);
        }
#pragma unroll
        for (int j = 0; j < 8; j++) {
            sum[j] += v[j];
            ssq[j] = fmaf(v[j], v[j], ssq[j]);
        }
        *(float4*)&g_h0[row*Cc + tn*8]     = make_float4(v[0],v[1],v[2],v[3]);
        *(float4*)&g_h0[row*Cc + tn*8 + 4] = make_float4(v[4],v[5],v[6],v[7]);
    }
    __syncthreads();
    float* st = smem_f;                     // reuse: [128ch][16tm] sum, +2048 ssq
#pragma unroll
    for (int j = 0; j < 8; j++) {
        st[(tn*8+j)*16 + tm]        = sum[j];
        st[2048 + (tn*8+j)*16 + tm] = ssq[j];
    }
    __syncthreads();
    if (t < Cc) {
        float s = 0.f, q = 0.f;
        for (int r = 0; r < 16; r++) { s += st[t*16+r]; q += st[2048 + t*16 + r]; }
        g_partS0[t*GBLKS + blk] = s;
        g_partQ0[t*GBLKS + blk] = q;
    }
}

// ============================================================================
// 4) BN stat reduce -> affine. 128 blocks (one per channel) x 256 threads,
//    coalesced reads, deterministic fp64 accumulation.
// ============================================================================
__global__ __launch_bounds__(256) void stats_kernel(int layer,
                                                    const float* __restrict__ gamma,
                                                    const float* __restrict__ beta)
{
    const float* PS = layer ? g_partS1 : g_partS0;
    const float* PQ = layer ? g_partQ1 : g_partQ0;
    float* aff = layer ? g_aff1 : g_aff0;
    const int c = blockIdx.x;
    const int t = threadIdx.x;
    double s = 0.0, q = 0.0;
    for (int i = t; i < GBLKS; i += 256) {
        s += (double)PS[c*GBLKS + i];
        q += (double)PQ[c*GBLKS + i];
    }
#pragma unroll
    for (int o = 16; o; o >>= 1) {
        s += __shfl_xor_sync(FULLM, s, o);
        q += __shfl_xor_sync(FULLM, q, o);
    }
    __shared__ double sw[16];
    int lane = t & 31, wid = t >> 5;
    if (lane == 0) { sw[wid*2] = s; sw[wid*2+1] = q; }
    __syncthreads();
    if (t == 0) {
        double S = 0.0, Q = 0.0;
        for (int w = 0; w < 8; w++) { S += sw[w*2]; Q += sw[w*2+1]; }
        double cnt = (double)MTOT;
        double mean = S / cnt;
        double var = Q / cnt - mean*mean;
        float a = gamma[c] * (float)(1.0 / sqrt(var + 1e-5));
        aff[c] = a;
        aff[Cc + c] = __fsub_rn(beta[c], (float)mean * a);
    }
}

// ============================================================================
// 5) Layer1 GEMM (K=128): A = relu(affine0(h0)) dup-packed, W = w1. + BN1.
// ============================================================================
#define G1_SMEM (128*128*8 + 128*128*4)

__global__ __launch_bounds__(256,1) void gemm1_kernel(const float* __restrict__ w1,
                                                      const float* __restrict__ b1)
{
    extern __shared__ float smem_f[];
    ull*   AD = (ull*)smem_f;                      // [128][128] dup-packed
    float* WS = smem_f + 128*128*2;                // [128][128]
    const int t = threadIdx.x;
    const int blk = blockIdx.x;

    for (int i = t; i < Cc*Cc; i += 256) {         // w1: [C][C]
        int c = i >> 7, f = i & 127;
        WS[f*128 + c] = w1[i];
    }
    {
        int m = t & 127, half = t >> 7;
        size_t R = (size_t)blk*128 + m;
        const float* hrow = g_h0 + R*Cc + half*64;
        for (int f = 0; f < 64; f += 4) {
            float4 v = *(const float4*)(hrow + f);
            int fg = half*64 + f;
            AD[(fg+0)*128+m] = fdup_bits(fmaxf(fmaf(g_aff0[fg+0], v.x, g_aff0[Cc+fg+0]), 0.f));
            AD[(fg+1)*128+m] = fdup_bits(fmaxf(fmaf(g_aff0[fg+1], v.y, g_aff0[Cc+fg+1]), 0.f));
            AD[(fg+2)*128+m] = fdup_bits(fmaxf(fmaf(g_aff0[fg+2], v.z, g_aff0[Cc+fg+2]), 0.f));
            AD[(fg+3)*128+m] = fdup_bits(fmaxf(fmaf(g_aff0[fg+3], v.w, g_aff0[Cc+fg+3]), 0.f));
        }
    }
    __syncthreads();

    const int tn = t & 15, tm = t >> 4;
    ull accp[8][4];
#pragma unroll
    for (int i = 0; i < 8; i++)
#pragma unroll
        for (int j = 0; j < 4; j++) accp[i][j] = 0;

    for (int kk = 0; kk < Cc; kk++) {
        ulonglong2 a01 = *(const ulonglong2*)(AD + kk*128 + tm*8);
        ulonglong2 a23 = *(const ulonglong2*)(AD + kk*128 + tm*8 + 2);
        ulonglong2 a45 = *(const ulonglong2*)(AD + kk*128 + tm*8 + 4);
        ulonglong2 a67 = *(const ulonglong2*)(AD + kk*128 + tm*8 + 6);
        ulonglong2 wA  = *(const ulonglong2*)(WS + kk*128 + tn*8);
        ulonglong2 wB  = *(const ulonglong2*)(WS + kk*128 + tn*8 + 4);
        ull a[8] = {a01.x,a01.y,a23.x,a23.y,a45.x,a45.y,a67.x,a67.y};
        ull w[4] = {wA.x, wA.y, wB.x, wB.y};
#pragma unroll
        for (int i = 0; i < 8; i++)
#pragma unroll
            for (int j = 0; j < 4; j++) accp[i][j] = f2fma(a[i], w[j], accp[i][j]);
    }

    float bb[8], sum[8], ssq[8];
#pragma unroll
    for (int j = 0; j < 8; j++) { bb[j] = b1[tn*8+j]; sum[j]=0.f; ssq[j]=0.f; }
#pragma unroll
    for (int i = 0; i < 8; i++) {
        size_t row = (size_t)blk*128 + tm*8 + i;
        float v[8];
#pragma unroll
        for (int j = 0; j < 4; j++) {
            float2 u = funpack(accp[i][j]);
            v[2*j]   = __fadd_rn(u.x, bb[2*j]);
            v[2*j+1] = __fadd_rn(u.y, bb[2*j+1]);
        }
#pragma unroll
        for (int j = 0; j < 8; j++) {
            sum[j] += v[j];
            ssq[j] = fmaf(v[j], v[j], ssq[j]);
        }
        *(float4*)&g_h1[row*Cc + tn*8]     = make_float4(v[0],v[1],v[2],v[3]);
        *(float4*)&g_h1[row*Cc + tn*8 + 4] = make_float4(v[4],v[5],v[6],v[7]);
    }
    __syncthreads();
    float* st = smem_f;
#pragma unroll
    for (int j = 0; j < 8; j++) {
        st[(tn*8+j)*16 + tm]        = sum[j];
        st[2048 + (tn*8+j)*16 + tm] = ssq[j];
    }
    __syncthreads();
    if (t < Cc) {
        float s = 0.f, q = 0.f;
        for (int r = 0; r < 16; r++) { s += st[t*16+r]; q += st[2048 + t*16 + r]; }
        g_partS1[t*GBLKS + blk] = s;
        g_partQ1[t*GBLKS + blk] = q;
    }
}

// ============================================================================
// 6) relu(affine1(h1)) then max over K -> new_features
// ============================================================================
__global__ __launch_bounds__(256) void final_kernel(float* __restrict__ out)
{
    int gid = blockIdx.x*256 + threadIdx.x;     // B*S*C = 1,048,576
    int c = gid & 127, bs = gid >> 7;
    float a = g_aff1[c], b = g_aff1[Cc + c];
    float m = -3.4e38f;
#pragma unroll
    for (int k = 0; k < Kc; k++) {
        float h = g_h1[((size_t)(bs*Kc + k))*Cc + c];
        float v = fmaxf(fmaf(a, h, b), 0.f);
        m = fmaxf(m, v);
    }
    out[Bc*Sc*3 + gid] = m;
}

// ============================================================================
extern "C" void kernel_launch(void* const* d_in, const int* in_sizes, int n_in,
                              void* d_out, int out_size)
{
    const float* xyz  = (const float*)d_in[0];
    const float* feat = (const float*)d_in[1];
    const float* w0   = (const float*)d_in[2];
    const float* b0   = (const float*)d_in[3];
    const float* g0   = (const float*)d_in[4];
    const float* be0  = (const float*)d_in[5];
    const float* w1   = (const float*)d_in[6];
    const float* b1   = (const float*)d_in[7];
    const float* g1   = (const float*)d_in[8];
    const float* be1  = (const float*)d_in[9];
    float* out = (float*)d_out;

    cudaFuncSetAttribute(fps_kernel,   cudaFuncAttributeMaxDynamicSharedMemorySize, FPS_SMEM);
    cudaFuncSetAttribute(knn_kernel,   cudaFuncAttributeMaxDynamicSharedMemorySize, KNN_SMEM);
    cudaFuncSetAttribute(gemm0_kernel, cudaFuncAttributeMaxDynamicSharedMemorySize, G0_SMEM);
    cudaFuncSetAttribute(gemm1_kernel, cudaFuncAttributeMaxDynamicSharedMemorySize, G1_SMEM);

    fps_kernel  <<<Bc, 1024, FPS_SMEM>>>(xyz, out);
    knn_kernel  <<<128, 256, KNN_SMEM>>>(xyz, out);
    gemm0_kernel<<<GBLKS, 256, G0_SMEM>>>(xyz, feat, w0, b0, out);
    stats_kernel<<<Cc, 256>>>(0, g0, be0);
    gemm1_kernel<<<GBLKS, 256, G1_SMEM>>>(w1, b1);
    stats_kernel<<<Cc, 256>>>(1, g1, be1);
    final_kernel<<<(Bc*Sc*Cc)/256, 256>>>(out);
}

// round 7
// speedup vs baseline: 1.2054x; 1.0260x over previous
#include <cuda_runtime.h>
#include <cstdint>

// Problem constants
#define Bc 4
#define Nc 8192
#define Fc 64
#define Sc 2048
#define Kc 16
#define Cc 128
#define MTOT (Bc*Sc*Kc)          // 131072 rows through the MLP
#define GBLKS (MTOT/128)         // 1024 gemm blocks
#define FULLM 0xffffffffu

typedef unsigned long long ull;

// -------- scratch (static device allocations; no cudaMalloc allowed) --------
__device__ float g_h0[(size_t)MTOT*Cc];   // 64 MB, pre-BN layer0 output
__device__ float g_h1[(size_t)MTOT*Cc];   // 64 MB, pre-BN layer1 output
__device__ int   g_knn[Bc*Sc*Kc];
__device__ float g_partS0[Cc*GBLKS];      // [c][blk] coalesced for stats
__device__ float g_partQ0[Cc*GBLKS];
__device__ float g_partS1[Cc*GBLKS];
__device__ float g_partQ1[Cc*GBLKS];
__device__ float g_aff0[2*Cc];            // [a..., b...] affine for relu(bn)
__device__ float g_aff1[2*Cc];

// ---------------- f32x2 packed helpers (sm_100+) ----------------
__device__ __forceinline__ ull f2add(ull a, ull b){
    ull r; asm("add.rn.f32x2 %0,%1,%2;" : "=l"(r) : "l"(a), "l"(b)); return r;
}
__device__ __forceinline__ ull f2mul(ull a, ull b){
    ull r; asm("mul.rn.f32x2 %0,%1,%2;" : "=l"(r) : "l"(a), "l"(b)); return r;
}
__device__ __forceinline__ ull f2fma(ull a, ull b, ull c){
    ull r; asm("fma.rn.f32x2 %0,%1,%2,%3;" : "=l"(r) : "l"(a), "l"(b), "l"(c)); return r;
}
__device__ __forceinline__ ull fpack(float lo, float hi){
    ull r; asm("mov.b64 %0,{%1,%2};" : "=l"(r) : "f"(lo), "f"(hi)); return r;
}
__device__ __forceinline__ float2 funpack(ull p){
    float2 f; asm("mov.b64 {%0,%1},%2;" : "=f"(f.x), "=f"(f.y) : "l"(p)); return f;
}
__device__ __forceinline__ ull fdup_bits(float v){
    unsigned ub = __float_as_uint(v);
    return ((ull)ub << 32) | ub;
}

// ---------------- warp redux helpers (Ampere+) ----------------
__device__ __forceinline__ unsigned redux_max_u32(unsigned v){
    unsigned r, m = FULLM;
    asm volatile("redux.sync.max.u32 %0, %1, %2;" : "=r"(r) : "r"(v), "r"(m));
    return r;
}
__device__ __forceinline__ unsigned redux_min_u32(unsigned v){
    unsigned r, m = FULLM;
    asm volatile("redux.sync.min.u32 %0, %1, %2;" : "=r"(r) : "r"(v), "r"(m));
    return r;
}

// ---------------- cluster helpers ----------------
__device__ __forceinline__ uint32_t smem_u32(const void* p){
    uint32_t a;
    asm("{ .reg .u64 t; cvta.to.shared.u64 t, %1; cvt.u32.u64 %0, t; }"
        : "=r"(a) : "l"(p));
    return a;
}
__device__ __forceinline__ uint32_t ctarank(){
    uint32_t r; asm("mov.u32 %0, %%cluster_ctarank;" : "=r"(r)); return r;
}
__device__ __forceinline__ void cluster_sync(){
    asm volatile("barrier.cluster.arrive.aligned;" ::: "memory");
    asm volatile("barrier.cluster.wait.aligned;" ::: "memory");
}
__device__ __forceinline__ uint32_t mapa_addr(uint32_t local, uint32_t peer){
    uint32_t r;
    asm("mapa.shared::cluster.u32 %0, %1, %2;" : "=r"(r) : "r"(local), "r"(peer));
    return r;
}
__device__ __forceinline__ void st_relaxed_cluster_u64(uint32_t raddr, ull v){
    asm volatile("st.relaxed.cluster.shared::cluster.u64 [%0], %1;"
                 :: "r"(raddr), "l"(v) : "memory");
}
__device__ __forceinline__ ull ld_relaxed_local_u64(uint32_t addr){
    ull v;
    asm volatile("ld.relaxed.cluster.shared::cta.u64 %0, [%1];"
                 : "=l"(v) : "r"(addr) : "memory");
    return v;
}

// ============================================================================
// 1) Farthest point sampling: 4-CTA cluster per batch, 512 thr x 4 pts/CTA.
//    Exchange = seq-tagged 64-bit relaxed atomics (flag+payload in one word,
//    no fences/mbarriers), polled by WARP 0 ONLY; winner broadcast via smem.
//    Key = valbits<<32 | (8191-idx)<<13 | seq(13b): orders by value desc then
//    smallest index (exact jnp.argmax tie-break); seq equal within an iter.
//    Distance math bit-identical: d=((dx*dx+dy*dy)+dz*dz), md=min(md,d).
// ============================================================================
#define FPS_CLUS 4
#define FPS_OFF_PART  (3*Nc*4)                   // ull[2][16]
#define FPS_OFF_SLOT  (FPS_OFF_PART + 2*16*8)    // ull[2][4]
#define FPS_OFF_BCAST (FPS_OFF_SLOT + 2*4*8)     // ull[2]
#define FPS_SMEM      (FPS_OFF_BCAST + 2*8 + 16)

__global__ __launch_bounds__(512,1) __cluster_dims__(FPS_CLUS,1,1)
void fps_kernel(const float* __restrict__ xyz, float* __restrict__ out)
{
    extern __shared__ float smem_f[];
    float* X = smem_f;
    float* Y = smem_f + Nc;
    float* Z = smem_f + 2*Nc;
    const uint32_t sbase = smem_u32(smem_f);
    ull* part  = (ull*)((char*)smem_f + FPS_OFF_PART);   // [2][16]
    ull* slot  = (ull*)((char*)smem_f + FPS_OFF_SLOT);   // [2][4]
    ull* bcast = (ull*)((char*)smem_f + FPS_OFF_BCAST);  // [2]
    const uint32_t slot_a = sbase + FPS_OFF_SLOT;

    const int t = threadIdx.x;
    const int lane = t & 31, wid = t >> 5;
    const uint32_t rank = ctarank();
    const int b = blockIdx.x / FPS_CLUS;

    const float* base = xyz + (size_t)b*Nc*3;
    float* oxyz = out + (size_t)b*Sc*3;

    // full cloud copy for winner lookup
    for (int p = t; p < Nc; p += 512) {
        X[p] = base[p*3+0]; Y[p] = base[p*3+1]; Z[p] = base[p*3+2];
    }
    if (t < 8) slot[t] = 0;    // seq starts at 1; 0 never matches
    __syncthreads();
    cluster_sync();            // smem + zeroed slots visible cluster-wide

    // this CTA's 4 points/thread (2 packed pairs)
    const int pbase = (int)rank*2048 + t*4;
    ull px2[2], py2[2], pz2[2];
    float md[4];
#pragma unroll
    for (int jj = 0; jj < 2; jj++) {
        int p = pbase + jj*2;
        px2[jj] = fpack(X[p], X[p+1]);
        py2[jj] = fpack(Y[p], Y[p+1]);
        pz2[jj] = fpack(Z[p], Z[p+1]);
        md[2*jj] = 1e10f; md[2*jj+1] = 1e10f;
    }

    float cx = X[0], cy = Y[0], cz = Z[0];

    for (int s = 0; s < Sc; s++) {
        if (rank == 0 && t == 0) {
            oxyz[s*3+0]=cx; oxyz[s*3+1]=cy; oxyz[s*3+2]=cz;
        }
        if (s == Sc-1) break;

        // x - c == x + (-c) exactly in IEEE754
        ull ncx = fdup_bits(-cx), ncy = fdup_bits(-cy), ncz = fdup_bits(-cz);

        float best = -1.0f; int bidx = 0;
#pragma unroll
        for (int jj = 0; jj < 2; jj++) {
            ull dx = f2add(px2[jj], ncx);
            ull dy = f2add(py2[jj], ncy);
            ull dz = f2add(pz2[jj], ncz);
            ull d2 = f2add(f2add(f2mul(dx,dx), f2mul(dy,dy)), f2mul(dz,dz));
            float2 d = funpack(d2);
            float m0 = fminf(md[2*jj],   d.x); md[2*jj]   = m0;
            float m1 = fminf(md[2*jj+1], d.y); md[2*jj+1] = m1;
            if (m0 > best) { best = m0; bidx = pbase + 2*jj; }      // strict >
            if (m1 > best) { best = m1; bidx = pbase + 2*jj + 1; }
        }

        const int ib = s & 1;
        const unsigned seq = (unsigned)((s + 1) & 0x1FFF);

        // stage 1: warp argmax (value desc, then smallest index)
        unsigned ub = __float_as_uint(best);
        unsigned wb = redux_max_u32(ub);
        unsigned cand = (ub == wb) ? (unsigned)bidx : FULLM;
        unsigned wi = redux_min_u32(cand);
        if (lane == 0)
            part[ib*16 + wid] = ((ull)wb << 32)
                              | ((ull)(unsigned)(8191 - wi) << 13) | seq;
        __syncthreads();

        if (wid == 0) {
            // stage 2: reduce 16 warp partials (slot order == idx-block order)
            ull k = part[ib*16 + (lane & 15)];
            unsigned v  = (unsigned)(k >> 32);
            unsigned vm = redux_max_u32(v);
            unsigned lo = (v == vm) ? (unsigned)k : 0u;  // bigger lo == smaller idx
            unsigned lom = redux_max_u32(lo);

            // publish CTA key to all 4 CTAs' slot[ib][rank] (relaxed, one word)
            if (lane < FPS_CLUS) {
                ull kcta = ((ull)vm << 32) | lom;
                uint32_t ra = mapa_addr(slot_a + (ib*4 + rank)*8, (uint32_t)lane);
                st_relaxed_cluster_u64(ra, kcta);
            }

            // poll local slots (only this warp touches the LSU with polls)
            uint32_t pa = slot_a + (ib*4 + (lane & 3))*8;
            ull kj;
            do { kj = ld_relaxed_local_u64(pa); } while ((unsigned)(kj & 0x1FFF) != seq);

            // max over the 4 slot keys
            unsigned v2  = (unsigned)(kj >> 32);
            unsigned vm2 = redux_max_u32(v2);
            unsigned lo2 = (v2 == vm2) ? (unsigned)kj : 0u;
            unsigned lom2 = redux_max_u32(lo2);
            if (lane == 0) bcast[ib] = ((ull)vm2 << 32) | lom2;
        }
        __syncthreads();

        ull kw = bcast[ib];
        int w = 8191 - (int)((kw >> 13) & 0x1FFF);
        cx = X[w]; cy = Y[w]; cz = Z[w];
    }
    cluster_sync();
}

// ============================================================================
// 2) Brute-force KNN (K=16). 64 queries per CTA, 4 threads per query, each
//    scans a 2048-point chunk; exact lex-ordered merge of 4 stable top-16s.
//    d2 = (|q|^2 + |p|^2) - 2*q.p   (exact ref op order; d2 is never -0)
// ============================================================================
#define KNN_SMEM (Nc*16 + 64*64*8)

__device__ __forceinline__ unsigned okey(float f){
    unsigned u = __float_as_uint(f);
    return ((int)u < 0) ? ~u : (u | 0x80000000u);   // monotone order-preserving
}

__global__ __launch_bounds__(256,1) void knn_kernel(const float* __restrict__ xyz,
                                                    const float* __restrict__ newxyz)
{
    extern __shared__ float smem_f[];
    float4* tile = (float4*)smem_f;
    ull* merge = (ull*)(smem_f + Nc*4);
    const int blk = blockIdx.x;      // 128 blocks = 4 batches * 32
    const int b = blk >> 5;
    const int qbase = (blk & 31) * 64;
    const float* base = xyz + (size_t)b*Nc*3;

    for (int p = threadIdx.x; p < Nc; p += 256) {
        float x = base[p*3], y = base[p*3+1], z = base[p*3+2];
        float sq = __fadd_rn(__fadd_rn(__fmul_rn(x,x), __fmul_rn(y,y)), __fmul_rn(z,z));
        tile[p] = make_float4(x, y, z, sq);
    }
    __syncthreads();

    const int q = threadIdx.x & 63;
    const int ch = threadIdx.x >> 6;             // chunk 0..3
    const int qi = b*Sc + qbase + q;
    float qx = newxyz[qi*3], qy = newxyz[qi*3+1], qz = newxyz[qi*3+2];
    float sqq = __fadd_rn(__fadd_rn(__fmul_rn(qx,qx), __fmul_rn(qy,qy)), __fmul_rn(qz,qz));

    float dist[Kc]; int ids[Kc];
#pragma unroll
    for (int i = 0; i < Kc; i++) { dist[i] = 3.4e38f; ids[i] = 0; }
    float kth = 3.4e38f;

    const int p0 = ch*2048;
    for (int p = p0; p < p0 + 2048; p++) {
        float4 v = tile[p];
        float dot = __fadd_rn(__fadd_rn(__fmul_rn(qx,v.x), __fmul_rn(qy,v.y)),
                              __fmul_rn(qz,v.z));
        float d2 = __fsub_rn(__fadd_rn(sqq, v.w), __fadd_rn(dot, dot));
        if (d2 < kth) {
            int j = Kc-1;
            while (j > 0 && dist[j-1] > d2) {   // stable insertion
                dist[j] = dist[j-1]; ids[j] = ids[j-1]; j--;
            }
            dist[j] = d2; ids[j] = p;
            kth = dist[Kc-1];
        }
    }
    // store lex-sorted packed list
    ull* mylist = merge + q*64 + ch*16;
#pragma unroll
    for (int i = 0; i < Kc; i++)
        mylist[i] = ((ull)okey(dist[i]) << 32) | (unsigned)ids[i];
    __syncthreads();

    if (threadIdx.x < 64) {
        int mq = threadIdx.x;
        const ull* L = merge + mq*64;
        int h0 = 0, h1 = 16, h2 = 32, h3 = 48;
        int oq = (b*Sc + qbase + mq)*Kc;
#pragma unroll
        for (int r = 0; r < Kc; r++) {
            ull k0 = L[h0], k1 = L[h1], k2 = L[h2], k3 = L[h3];
            ull ka = (k0 <= k1) ? k0 : k1;
            ull kb = (k2 <= k3) ? k2 : k3;
            ull kw = (ka <= kb) ? ka : kb;
            g_knn[oq + r] = (int)(unsigned)kw;
            if (kw == k0) h0++; else if (kw == k1) h1++;
            else if (kw == k2) h2++; else h3++;
        }
    }
}

// ============================================================================
// 3) Gather + layer0 GEMM (M=131072, N=128, K=67) + BN-stat partials.
//    128x128 tile, 256 threads, 8x8 microtiles, packed f32x2 FFMA.
//    A stored duplicated (v,v) in smem so no per-k register dup.
// ============================================================================
#define G0_SMEM (68*128*8 + 68*128*4)

__global__ __launch_bounds__(256,2) void gemm0_kernel(const float* __restrict__ xyz,
                                                      const float* __restrict__ feat,
                                                      const float* __restrict__ w0,
                                                      const float* __restrict__ b0,
                                                      const float* __restrict__ newxyz)
{
    extern __shared__ float smem_f[];
    ull*   AD = (ull*)smem_f;                      // [68][128] dup-packed
    float* WS = smem_f + 68*128*2;                 // [68][128]
    const int t = threadIdx.x;
    const int blk = blockIdx.x;

    for (int i = t; i < Cc*67; i += 256) {         // w0: [C][67]
        int c = i / 67, f = i - c*67;
        WS[f*128 + c] = w0[i];
    }
    {
        int m = t & 127, half = t >> 7;
        int R = blk*128 + m;
        int bs = R >> 4;
        int b = bs >> 11;
        int nid = g_knn[R];
        const float* frow = feat + ((size_t)b*Nc + nid)*Fc;
        if (half == 0) {
            const float* prow = xyz + ((size_t)b*Nc + nid)*3;
            AD[0*128+m] = fdup_bits(__fsub_rn(prow[0], newxyz[bs*3+0]));
            AD[1*128+m] = fdup_bits(__fsub_rn(prow[1], newxyz[bs*3+1]));
            AD[2*128+m] = fdup_bits(__fsub_rn(prow[2], newxyz[bs*3+2]));
            for (int f = 0; f < 32; f += 4) {
                float4 v = *(const float4*)(frow + f);
                AD[(3+f)*128+m]=fdup_bits(v.x); AD[(4+f)*128+m]=fdup_bits(v.y);
                AD[(5+f)*128+m]=fdup_bits(v.z); AD[(6+f)*128+m]=fdup_bits(v.w);
            }
        } else {
            for (int f = 32; f < 64; f += 4) {
                float4 v = *(const float4*)(frow + f);
                AD[(3+f)*128+m]=fdup_bits(v.x); AD[(4+f)*128+m]=fdup_bits(v.y);
                AD[(5+f)*128+m]=fdup_bits(v.z); AD[(6+f)*128+m]=fdup_bits(v.w);
            }
        }
    }
    __syncthreads();

    const int tn = t & 15, tm = t >> 4;
    ull accp[8][4];
#pragma unroll
    for (int i = 0; i < 8; i++)
#pragma unroll
        for (int j = 0; j < 4; j++) accp[i][j] = 0;

    for (int kk = 0; kk < 67; kk++) {
        ulonglong2 a01 = *(const ulonglong2*)(AD + kk*128 + tm*8);
        ulonglong2 a23 = *(const ulonglong2*)(AD + kk*128 + tm*8 + 2);
        ulonglong2 a45 = *(const ulonglong2*)(AD + kk*128 + tm*8 + 4);
        ulonglong2 a67 = *(const ulonglong2*)(AD + kk*128 + tm*8 + 6);
        ulonglong2 wA  = *(const ulonglong2*)(WS + kk*128 + tn*8);
        ulonglong2 wB  = *(const ulonglong2*)(WS + kk*128 + tn*8 + 4);
        ull a[8] = {a01.x,a01.y,a23.x,a23.y,a45.x,a45.y,a67.x,a67.y};
        ull w[4] = {wA.x, wA.y, wB.x, wB.y};
#pragma unroll
        for (int i = 0; i < 8; i++)
#pragma unroll
            for (int j = 0; j < 4; j++) accp[i][j] = f2fma(a[i], w[j], accp[i][j]);
    }

    float bb[8], sum[8], ssq[8];
#pragma unroll
    for (int j = 0; j < 8; j++) { bb[j] = b0[tn*8+j]; sum[j]=0.f; ssq[j]=0.f; }
#pragma unroll
    for (int i = 0; i < 8; i++) {
        size_t row = (size_t)blk*128 + tm*8 + i;
        float v[8];
#pragma unroll
        for (int j = 0; j < 4; j++) {
            float2 u = funpack(accp[i][j]);
            v[2*j]   = __fadd_rn(u.x, bb[2*j]);
            v[2*j+1] = __fadd_rn(u.y, bb[2*j+1]);
        }
#pragma unroll
        for (int j = 0; j < 8; j++) {
            sum[j] += v[j];
            ssq[j] = fmaf(v[j], v[j], ssq[j]);
        }
        *(float4*)&g_h0[row*Cc + tn*8]     = make_float4(v[0],v[1],v[2],v[3]);
        *(float4*)&g_h0[row*Cc + tn*8 + 4] = make_float4(v[4],v[5],v[6],v[7]);
    }
    __syncthreads();
    float* st = smem_f;                     // reuse: [128ch][16tm] sum, +2048 ssq
#pragma unroll
    for (int j = 0; j < 8; j++) {
        st[(tn*8+j)*16 + tm]        = sum[j];
        st[2048 + (tn*8+j)*16 + tm] = ssq[j];
    }
    __syncthreads();
    if (t < Cc) {
        float s = 0.f, q = 0.f;
        for (int r = 0; r < 16; r++) { s += st[t*16+r]; q += st[2048 + t*16 + r]; }
        g_partS0[t*GBLKS + blk] = s;
        g_partQ0[t*GBLKS + blk] = q;
    }
}

// ============================================================================
// 4) BN stat reduce -> affine. 128 blocks (one per channel) x 256 threads,
//    coalesced reads, deterministic fp64 accumulation.
// ============================================================================
__global__ __launch_bounds__(256) void stats_kernel(int layer,
                                                    const float* __restrict__ gamma,
                                                    const float* __restrict__ beta)
{
    const float* PS = layer ? g_partS1 : g_partS0;
    const float* PQ = layer ? g_partQ1 : g_partQ0;
    float* aff = layer ? g_aff1 : g_aff0;
    const int c = blockIdx.x;
    const int t = threadIdx.x;
    double s = 0.0, q = 0.0;
    for (int i = t; i < GBLKS; i += 256) {
        s += (double)PS[c*GBLKS + i];
        q += (double)PQ[c*GBLKS + i];
    }
#pragma unroll
    for (int o = 16; o; o >>= 1) {
        s += __shfl_xor_sync(FULLM, s, o);
        q += __shfl_xor_sync(FULLM, q, o);
    }
    __shared__ double sw[16];
    int lane = t & 31, wid = t >> 5;
    if (lane == 0) { sw[wid*2] = s; sw[wid*2+1] = q; }
    __syncthreads();
    if (t == 0) {
        double S = 0.0, Q = 0.0;
        for (int w = 0; w < 8; w++) { S += sw[w*2]; Q += sw[w*2+1]; }
        double cnt = (double)MTOT;
        double mean = S / cnt;
        double var = Q / cnt - mean*mean;
        float a = gamma[c] * (float)(1.0 / sqrt(var + 1e-5));
        aff[c] = a;
        aff[Cc + c] = __fsub_rn(beta[c], (float)mean * a);
    }
}

// ============================================================================
// 5) Layer1 GEMM (K=128): A = relu(affine0(h0)) dup-packed, W = w1. + BN1.
// ============================================================================
#define G1_SMEM (128*128*8 + 128*128*4)

__global__ __launch_bounds__(256,1) void gemm1_kernel(const float* __restrict__ w1,
                                                      const float* __restrict__ b1)
{
    extern __shared__ float smem_f[];
    ull*   AD = (ull*)smem_f;                      // [128][128] dup-packed
    float* WS = smem_f + 128*128*2;                // [128][128]
    const int t = threadIdx.x;
    const int blk = blockIdx.x;

    for (int i = t; i < Cc*Cc; i += 256) {         // w1: [C][C]
        int c = i >> 7, f = i & 127;
        WS[f*128 + c] = w1[i];
    }
    {
        int m = t & 127, half = t >> 7;
        size_t R = (size_t)blk*128 + m;
        const float* hrow = g_h0 + R*Cc + half*64;
        for (int f = 0; f < 64; f += 4) {
            float4 v = *(const float4*)(hrow + f);
            int fg = half*64 + f;
            AD[(fg+0)*128+m] = fdup_bits(fmaxf(fmaf(g_aff0[fg+0], v.x, g_aff0[Cc+fg+0]), 0.f));
            AD[(fg+1)*128+m] = fdup_bits(fmaxf(fmaf(g_aff0[fg+1], v.y, g_aff0[Cc+fg+1]), 0.f));
            AD[(fg+2)*128+m] = fdup_bits(fmaxf(fmaf(g_aff0[fg+2], v.z, g_aff0[Cc+fg+2]), 0.f));
            AD[(fg+3)*128+m] = fdup_bits(fmaxf(fmaf(g_aff0[fg+3], v.w, g_aff0[Cc+fg+3]), 0.f));
        }
    }
    __syncthreads();

    const int tn = t & 15, tm = t >> 4;
    ull accp[8][4];
#pragma unroll
    for (int i = 0; i < 8; i++)
#pragma unroll
        for (int j = 0; j < 4; j++) accp[i][j] = 0;

    for (int kk = 0; kk < Cc; kk++) {
        ulonglong2 a01 = *(const ulonglong2*)(AD + kk*128 + tm*8);
        ulonglong2 a23 = *(const ulonglong2*)(AD + kk*128 + tm*8 + 2);
        ulonglong2 a45 = *(const ulonglong2*)(AD + kk*128 + tm*8 + 4);
        ulonglong2 a67 = *(const ulonglong2*)(AD + kk*128 + tm*8 + 6);
        ulonglong2 wA  = *(const ulonglong2*)(WS + kk*128 + tn*8);
        ulonglong2 wB  = *(const ulonglong2*)(WS + kk*128 + tn*8 + 4);
        ull a[8] = {a01.x,a01.y,a23.x,a23.y,a45.x,a45.y,a67.x,a67.y};
        ull w[4] = {wA.x, wA.y, wB.x, wB.y};
#pragma unroll
        for (int i = 0; i < 8; i++)
#pragma unroll
            for (int j = 0; j < 4; j++) accp[i][j] = f2fma(a[i], w[j], accp[i][j]);
    }

    float bb[8], sum[8], ssq[8];
#pragma unroll
    for (int j = 0; j < 8; j++) { bb[j] = b1[tn*8+j]; sum[j]=0.f; ssq[j]=0.f; }
#pragma unroll
    for (int i = 0; i < 8; i++) {
        size_t row = (size_t)blk*128 + tm*8 + i;
        float v[8];
#pragma unroll
        for (int j = 0; j < 4; j++) {
            float2 u = funpack(accp[i][j]);
            v[2*j]   = __fadd_rn(u.x, bb[2*j]);
            v[2*j+1] = __fadd_rn(u.y, bb[2*j+1]);
        }
#pragma unroll
        for (int j = 0; j < 8; j++) {
            sum[j] += v[j];
            ssq[j] = fmaf(v[j], v[j], ssq[j]);
        }
        *(float4*)&g_h1[row*Cc + tn*8]     = make_float4(v[0],v[1],v[2],v[3]);
        *(float4*)&g_h1[row*Cc + tn*8 + 4] = make_float4(v[4],v[5],v[6],v[7]);
    }
    __syncthreads();
    float* st = smem_f;
#pragma unroll
    for (int j = 0; j < 8; j++) {
        st[(tn*8+j)*16 + tm]        = sum[j];
        st[2048 + (tn*8+j)*16 + tm] = ssq[j];
    }
    __syncthreads();
    if (t < Cc) {
        float s = 0.f, q = 0.f;
        for (int r = 0; r < 16; r++) { s += st[t*16+r]; q += st[2048 + t*16 + r]; }
        g_partS1[t*GBLKS + blk] = s;
        g_partQ1[t*GBLKS + blk] = q;
    }
}

// ============================================================================
// 6) relu(affine1(h1)) then max over K -> new_features
// ============================================================================
__global__ __launch_bounds__(256) void final_kernel(float* __restrict__ out)
{
    int gid = blockIdx.x*256 + threadIdx.x;     // B*S*C = 1,048,576
    int c = gid & 127, bs = gid >> 7;
    float a = g_aff1[c], b = g_aff1[Cc + c];
    float m = -3.4e38f;
#pragma unroll
    for (int k = 0; k < Kc; k++) {
        float h = g_h1[((size_t)(bs*Kc + k))*Cc + c];
        float v = fmaxf(fmaf(a, h, b), 0.f);
        m = fmaxf(m, v);
    }
    out[Bc*Sc*3 + gid] = m;
}

// ============================================================================
extern "C" void kernel_launch(void* const* d_in, const int* in_sizes, int n_in,
                              void* d_out, int out_size)
{
    const float* xyz  = (const float*)d_in[0];
    const float* feat = (const float*)d_in[1];
    const float* w0   = (const float*)d_in[2];
    const float* b0   = (const float*)d_in[3];
    const float* g0   = (const float*)d_in[4];
    const float* be0  = (const float*)d_in[5];
    const float* w1   = (const float*)d_in[6];
    const float* b1   = (const float*)d_in[7];
    const float* g1   = (const float*)d_in[8];
    const float* be1  = (const float*)d_in[9];
    float* out = (float*)d_out;

    cudaFuncSetAttribute(fps_kernel,   cudaFuncAttributeMaxDynamicSharedMemorySize, FPS_SMEM);
    cudaFuncSetAttribute(knn_kernel,   cudaFuncAttributeMaxDynamicSharedMemorySize, KNN_SMEM);
    cudaFuncSetAttribute(gemm0_kernel, cudaFuncAttributeMaxDynamicSharedMemorySize, G0_SMEM);
    cudaFuncSetAttribute(gemm1_kernel, cudaFuncAttributeMaxDynamicSharedMemorySize, G1_SMEM);

    fps_kernel  <<<Bc*FPS_CLUS, 512, FPS_SMEM>>>(xyz, out);
    knn_kernel  <<<128, 256, KNN_SMEM>>>(xyz, out);
    gemm0_kernel<<<GBLKS, 256, G0_SMEM>>>(xyz, feat, w0, b0, out);
    stats_kernel<<<Cc, 256>>>(0, g0, be0);
    gemm1_kernel<<<GBLKS, 256, G1_SMEM>>>(w1, b1);
    stats_kernel<<<Cc, 256>>>(1, g1, be1);
    final_kernel<<<(Bc*Sc*Cc)/256, 256>>>(out);
}